// round 4
// baseline (speedup 1.0000x reference)
#include <cuda_runtime.h>
#include <cuda_bf16.h>
#include <math.h>
#include <stdint.h>
#include <mma.h>

using namespace nvcuda;

// ---------------------------------------------------------------------------
// Problem constants
// ---------------------------------------------------------------------------
#define BATCH   4
#define SEQ     2048
#define EMBED   1024
#define HEADS   8
#define HDIM    128            // EMBED / HEADS
#define MROWS   (BATCH * SEQ)  // 8192
#define QKV_N   (3 * EMBED)    // 3072

// Scratch (__device__ globals: no allocation allowed anywhere)
__device__ float g_qkv[(size_t)BATCH * SEQ * QKV_N];   // [B,N,3D]
__device__ float g_att[(size_t)BATCH * SEQ * EMBED];   // [B,N,D]
__device__ float g_WqkvT[(size_t)QKV_N * EMBED];       // [3072,1024] K-major
__device__ float g_WprojT[(size_t)EMBED * EMBED];      // [1024,1024] K-major

// ---------------------------------------------------------------------------
// cp.async helpers (sm_80 PTX — safe on plain sm_103 target)
// ---------------------------------------------------------------------------
__device__ __forceinline__ uint32_t smem_u32(const void* p) {
    uint32_t a;
    asm("{ .reg .u64 t; cvta.to.shared.u64 t, %1; cvt.u32.u64 %0, t; }"
        : "=r"(a) : "l"(p));
    return a;
}
__device__ __forceinline__ void cp_async16(uint32_t s, const void* g) {
    asm volatile("cp.async.ca.shared.global [%0], [%1], 16;" :: "r"(s), "l"(g));
}
#define CP_COMMIT()  asm volatile("cp.async.commit_group;" ::: "memory")
#define CP_WAIT_1()  asm volatile("cp.async.wait_group 1;" ::: "memory")
#define CP_WAIT_0()  asm volatile("cp.async.wait_group 0;" ::: "memory")

// ---------------------------------------------------------------------------
// 3xTF32 wmma GEMM: C[M,N] = A[M,K] @ BT[N,K]^T + bias[N]  (~fp32 accuracy)
//   A row-major [M,K], BT K-major [N,K] (wmma matrix_b col_major).
//   CTA tile 128x128, 256 threads, 8 warps (2x4), warp tile 64x32.
//   K-tile 16, 2-stage cp.async pipeline.
//   Each operand split a = ah + al (tf32 halves); acc += Ah*Bh + Ah*Bl + Al*Bh.
// Smem (floats): stage s: As = s*6144 (128 rows x ld24), Bs = As + 3072;
//   bias tile (16x128) at 12288. Total 14336 floats = 56 KB.
// ---------------------------------------------------------------------------
#define G_LD     24
#define G_TK     16
#define G_STAGE_FLOATS ((128 + 128) * G_LD)      // 6144
#define G_BIAS_OFF     (2 * G_STAGE_FLOATS)      // 12288
#define G_SMEM_FLOATS  (G_BIAS_OFF + 16 * 128)   // 14336
#define G_SMEM_BYTES   (G_SMEM_FLOATS * 4)       // 57344

__global__ void __launch_bounds__(256)
gemm_wmma_3xtf32(const float* __restrict__ A, const float* __restrict__ BT,
                 const float* __restrict__ bias, float* __restrict__ C,
                 int M, int N, int K)
{
    extern __shared__ __align__(128) float sm[];
    float* biasS = sm + G_BIAS_OFF;

    const int tid  = threadIdx.x;
    const int warp = tid >> 5;
    const int wm   = warp >> 2;          // 0..1 : 64-row band
    const int wn   = warp & 3;           // 0..3 : 32-col band
    const int bm   = blockIdx.y * 128;
    const int bn   = blockIdx.x * 128;

    // Bias broadcast tile: biasS[r][c] = bias[bn + c]
    for (int i = tid; i < 16 * 128; i += 256)
        biasS[i] = bias[bn + (i & 127)];

    const uint32_t smb = smem_u32(sm);

    // Stage loader: 512 float4 chunks each for A and BT; 2 per thread each.
    auto load_tile = [&](int t) {
        const int st = t & 1;
        const int k0 = t * G_TK;
#pragma unroll
        for (int h = 0; h < 2; h++) {
            const int c   = tid + h * 256;
            const int row = c >> 2;
            const int q   = c & 3;
            uint32_t sa = smb + (uint32_t)(st * G_STAGE_FLOATS + row * G_LD + q * 4) * 4;
            cp_async16(sa,  A  + (size_t)(bm + row) * K + k0 + q * 4);
            uint32_t sb2 = smb + (uint32_t)(st * G_STAGE_FLOATS + 128 * G_LD
                                            + row * G_LD + q * 4) * 4;
            cp_async16(sb2, BT + (size_t)(bn + row) * K + k0 + q * 4);
        }
    };

    load_tile(0);
    CP_COMMIT();
    __syncthreads();                 // bias tile visible to all warps

    // Accumulators initialized with bias (race-free: after the barrier)
    wmma::fragment<wmma::accumulator, 16, 16, 8, float> acc[4][2];
#pragma unroll
    for (int i = 0; i < 4; i++)
#pragma unroll
        for (int j = 0; j < 2; j++)
            wmma::load_matrix_sync(acc[i][j],
                                   biasS + wn * 32 + j * 16, 128,
                                   wmma::mem_row_major);

    const int NT = K / G_TK;         // 64
    for (int t = 0; t < NT; t++) {
        if (t + 1 < NT) { load_tile(t + 1); CP_COMMIT(); CP_WAIT_1(); }
        else            { CP_WAIT_0(); }
        __syncthreads();

        const float* As = sm + (t & 1) * G_STAGE_FLOATS;
        const float* Bs = As + 128 * G_LD;

#pragma unroll
        for (int kk = 0; kk < G_TK; kk += 8) {
            wmma::fragment<wmma::matrix_a, 16, 16, 8,
                           wmma::precision::tf32, wmma::row_major> ah[4], al[4];
            wmma::fragment<wmma::matrix_b, 16, 16, 8,
                           wmma::precision::tf32, wmma::col_major> bh[2], bl[2];
#pragma unroll
            for (int i = 0; i < 4; i++) {
                wmma::load_matrix_sync(al[i],
                    As + (wm * 64 + i * 16) * G_LD + kk, G_LD);
#pragma unroll
                for (int e = 0; e < al[i].num_elements; e++) {
                    float v = al[i].x[e];
                    float h = wmma::__float_to_tf32(v);
                    ah[i].x[e] = h;
                    al[i].x[e] = wmma::__float_to_tf32(v - h);
                }
            }
#pragma unroll
            for (int j = 0; j < 2; j++) {
                wmma::load_matrix_sync(bl[j],
                    Bs + (wn * 32 + j * 16) * G_LD + kk, G_LD);
#pragma unroll
                for (int e = 0; e < bl[j].num_elements; e++) {
                    float v = bl[j].x[e];
                    float h = wmma::__float_to_tf32(v);
                    bh[j].x[e] = h;
                    bl[j].x[e] = wmma::__float_to_tf32(v - h);
                }
            }
#pragma unroll
            for (int i = 0; i < 4; i++)
#pragma unroll
                for (int j = 0; j < 2; j++) {
                    wmma::mma_sync(acc[i][j], ah[i], bh[j], acc[i][j]);
                    wmma::mma_sync(acc[i][j], ah[i], bl[j], acc[i][j]);
                    wmma::mma_sync(acc[i][j], al[i], bh[j], acc[i][j]);
                }
        }
        __syncthreads();
    }

    // Epilogue: direct global store (bias already in acc)
#pragma unroll
    for (int i = 0; i < 4; i++)
#pragma unroll
        for (int j = 0; j < 2; j++)
            wmma::store_matrix_sync(
                C + (size_t)(bm + wm * 64 + i * 16) * N + bn + wn * 32 + j * 16,
                acc[i][j], N, wmma::mem_row_major);
}

// ---------------------------------------------------------------------------
// Transpose: out[C][R] = in[R][C]   (R, C multiples of 32)
// ---------------------------------------------------------------------------
__global__ void transpose_kernel(const float* __restrict__ in,
                                 float* __restrict__ out, int R, int C)
{
    __shared__ float t[32][33];
    const int bx = blockIdx.x * 32;
    const int by = blockIdx.y * 32;
    const int x = bx + threadIdx.x;
#pragma unroll
    for (int i = threadIdx.y; i < 32; i += 8)
        t[i][threadIdx.x] = in[(size_t)(by + i) * C + x];
    __syncthreads();
    const int ox = by + threadIdx.x;
#pragma unroll
    for (int i = threadIdx.y; i < 32; i += 8)
        out[(size_t)(bx + i) * R + ox] = t[threadIdx.x][i];
}

// ---------------------------------------------------------------------------
// Flash attention (fp32 SIMT, online softmax) — unchanged from R1 (passing).
// ---------------------------------------------------------------------------
#define QS_OFF   0
#define KS_OFF   (128 * 68)
#define VS_OFF   (KS_OFF + 128 * 68)
#define SS_OFF   (VS_OFF + 64 * 128)
#define MS_OFF   (SS_OFF + 64 * 68)
#define LS_OFF   (MS_OFF + 64)
#define CS_OFF   (LS_OFF + 64)
#define FA_SMEM_FLOATS (CS_OFF + 64)
#define FA_SMEM_BYTES  (FA_SMEM_FLOATS * 4)

__global__ __launch_bounds__(256, 1)
void attention_kernel(const float* __restrict__ qkv, float* __restrict__ out)
{
    extern __shared__ float smf[];
    float* Qs  = smf + QS_OFF;
    float* Ks  = smf + KS_OFF;
    float* Vs  = smf + VS_OFF;
    float* Ss  = smf + SS_OFF;
    float* m_s = smf + MS_OFF;
    float* l_s = smf + LS_OFF;
    float* c_s = smf + CS_OFF;

    const int tid  = threadIdx.x;
    const int lane = tid & 31;
    const int warp = tid >> 5;
    const int tx   = tid & 15;
    const int ty   = tid >> 4;
    const int q0   = blockIdx.x * 64;
    const int h    = blockIdx.y;
    const int b    = blockIdx.z;

    const size_t base = (size_t)b * SEQ * QKV_N + (size_t)h * HDIM;
    const float* Qg = qkv + base;
    const float* Kg = qkv + base + EMBED;
    const float* Vg = qkv + base + 2 * EMBED;

    {
        const int d4 = (tid & 31) * 4;
#pragma unroll
        for (int pass = 0; pass < 8; pass++) {
            int qi = pass * 8 + warp;
            float4 v = *reinterpret_cast<const float4*>(
                Qg + (size_t)(q0 + qi) * QKV_N + d4);
            Qs[(d4 + 0) * 68 + qi] = v.x;
            Qs[(d4 + 1) * 68 + qi] = v.y;
            Qs[(d4 + 2) * 68 + qi] = v.z;
            Qs[(d4 + 3) * 68 + qi] = v.w;
        }
    }
    if (tid < 64) { m_s[tid] = -1e30f; l_s[tid] = 0.f; }

    float o[4][8];
#pragma unroll
    for (int i = 0; i < 4; i++)
#pragma unroll
        for (int j = 0; j < 8; j++) o[i][j] = 0.f;

    const float sc = 0.08838834764831845f;

    for (int kt = 0; kt < SEQ / 64; kt++) {
        {
            const int d4 = (tid & 31) * 4;
#pragma unroll
            for (int pass = 0; pass < 8; pass++) {
                int ki = pass * 8 + warp;
                size_t grow = (size_t)(kt * 64 + ki) * QKV_N + d4;
                float4 kv = *reinterpret_cast<const float4*>(Kg + grow);
                Ks[(d4 + 0) * 68 + ki] = kv.x;
                Ks[(d4 + 1) * 68 + ki] = kv.y;
                Ks[(d4 + 2) * 68 + ki] = kv.z;
                Ks[(d4 + 3) * 68 + ki] = kv.w;
                float4 vv = *reinterpret_cast<const float4*>(Vg + grow);
                *reinterpret_cast<float4*>(&Vs[ki * 128 + d4]) = vv;
            }
        }
        __syncthreads();

        float s[4][4];
#pragma unroll
        for (int i = 0; i < 4; i++)
#pragma unroll
            for (int j = 0; j < 4; j++) s[i][j] = 0.f;

#pragma unroll 4
        for (int kk = 0; kk < 128; kk++) {
            float4 qv = *reinterpret_cast<const float4*>(&Qs[kk * 68 + ty * 4]);
            float4 kv = *reinterpret_cast<const float4*>(&Ks[kk * 68 + tx * 4]);
            float qr[4] = {qv.x, qv.y, qv.z, qv.w};
            float kr[4] = {kv.x, kv.y, kv.z, kv.w};
#pragma unroll
            for (int i = 0; i < 4; i++)
#pragma unroll
                for (int j = 0; j < 4; j++)
                    s[i][j] = fmaf(qr[i], kr[j], s[i][j]);
        }
#pragma unroll
        for (int i = 0; i < 4; i++) {
            float4 v;
            v.x = s[i][0] * sc; v.y = s[i][1] * sc;
            v.z = s[i][2] * sc; v.w = s[i][3] * sc;
            *reinterpret_cast<float4*>(&Ss[(ty * 4 + i) * 68 + tx * 4]) = v;
        }
        __syncthreads();

#pragma unroll
        for (int rr = 0; rr < 8; rr++) {
            int r = warp * 8 + rr;
            float x0 = Ss[r * 68 + lane];
            float x1 = Ss[r * 68 + 32 + lane];
            float mx = fmaxf(x0, x1);
#pragma unroll
            for (int off = 16; off > 0; off >>= 1)
                mx = fmaxf(mx, __shfl_xor_sync(0xffffffffu, mx, off));
            float mo = m_s[r];
            float M  = fmaxf(mo, mx);
            float p0 = __expf(x0 - M);
            float p1 = __expf(x1 - M);
            Ss[r * 68 + lane]      = p0;
            Ss[r * 68 + 32 + lane] = p1;
            float sum = p0 + p1;
#pragma unroll
            for (int off = 16; off > 0; off >>= 1)
                sum += __shfl_xor_sync(0xffffffffu, sum, off);
            if (lane == 0) {
                float corr = __expf(mo - M);
                l_s[r] = l_s[r] * corr + sum;
                m_s[r] = M;
                c_s[r] = corr;
            }
        }
        __syncthreads();

        float cr[4];
#pragma unroll
        for (int i = 0; i < 4; i++) cr[i] = c_s[ty * 4 + i];
#pragma unroll
        for (int i = 0; i < 4; i++)
#pragma unroll
            for (int j = 0; j < 8; j++) o[i][j] *= cr[i];

#pragma unroll 4
        for (int ki = 0; ki < 64; ki++) {
            float p0 = Ss[(ty * 4 + 0) * 68 + ki];
            float p1 = Ss[(ty * 4 + 1) * 68 + ki];
            float p2 = Ss[(ty * 4 + 2) * 68 + ki];
            float p3 = Ss[(ty * 4 + 3) * 68 + ki];
            float4 v0 = *reinterpret_cast<const float4*>(&Vs[ki * 128 + tx * 4]);
            float4 v1 = *reinterpret_cast<const float4*>(&Vs[ki * 128 + 64 + tx * 4]);
            float vr[8] = {v0.x, v0.y, v0.z, v0.w, v1.x, v1.y, v1.z, v1.w};
            float pr[4] = {p0, p1, p2, p3};
#pragma unroll
            for (int i = 0; i < 4; i++)
#pragma unroll
                for (int j = 0; j < 8; j++)
                    o[i][j] = fmaf(pr[i], vr[j], o[i][j]);
        }
        __syncthreads();
    }

#pragma unroll
    for (int i = 0; i < 4; i++) {
        int r = ty * 4 + i;
        float inv = 1.f / l_s[r];
        float* orow = out + ((size_t)b * SEQ + (q0 + r)) * EMBED + h * HDIM;
        float4 o0, o1;
        o0.x = o[i][0] * inv; o0.y = o[i][1] * inv;
        o0.z = o[i][2] * inv; o0.w = o[i][3] * inv;
        o1.x = o[i][4] * inv; o1.y = o[i][5] * inv;
        o1.z = o[i][6] * inv; o1.w = o[i][7] * inv;
        *reinterpret_cast<float4*>(orow + tx * 4)      = o0;
        *reinterpret_cast<float4*>(orow + 64 + tx * 4) = o1;
    }
}

// ---------------------------------------------------------------------------
// kernel_launch
// ---------------------------------------------------------------------------
extern "C" void kernel_launch(void* const* d_in, const int* in_sizes, int n_in,
                              void* d_out, int out_size)
{
    const float* x     = (const float*)d_in[0];   // [4,2048,1024]
    const float* Wqkv  = (const float*)d_in[1];   // [1024,3072]
    const float* bqkv  = (const float*)d_in[2];   // [3072]
    const float* Wproj = (const float*)d_in[3];   // [1024,1024]
    const float* bproj = (const float*)d_in[4];   // [1024]
    float* out = (float*)d_out;

    void *p_qkv, *p_att, *p_wqT, *p_wpT;
    cudaGetSymbolAddress(&p_qkv, g_qkv);
    cudaGetSymbolAddress(&p_att, g_att);
    cudaGetSymbolAddress(&p_wqT, g_WqkvT);
    cudaGetSymbolAddress(&p_wpT, g_WprojT);
    float* qkv = (float*)p_qkv;
    float* att = (float*)p_att;
    float* wqT = (float*)p_wqT;
    float* wpT = (float*)p_wpT;

    cudaFuncSetAttribute(gemm_wmma_3xtf32,
                         cudaFuncAttributeMaxDynamicSharedMemorySize,
                         G_SMEM_BYTES);
    cudaFuncSetAttribute(attention_kernel,
                         cudaFuncAttributeMaxDynamicSharedMemorySize,
                         FA_SMEM_BYTES);

    // Weights -> K-major [N,K]
    transpose_kernel<<<dim3(QKV_N / 32, EMBED / 32), dim3(32, 8)>>>(
        Wqkv, wqT, EMBED, QKV_N);
    transpose_kernel<<<dim3(EMBED / 32, EMBED / 32), dim3(32, 8)>>>(
        Wproj, wpT, EMBED, EMBED);

    // GEMM1: qkv = x @ Wqkv + b   (3xTF32 wmma)
    gemm_wmma_3xtf32<<<dim3(QKV_N / 128, MROWS / 128), 256, G_SMEM_BYTES>>>(
        x, wqT, bqkv, qkv, MROWS, QKV_N, EMBED);

    // Attention (fp32 SIMT)
    attention_kernel<<<dim3(SEQ / 64, HEADS, BATCH), 256, FA_SMEM_BYTES>>>(
        qkv, att);

    // GEMM2: out = att @ Wproj + b   (3xTF32 wmma)
    gemm_wmma_3xtf32<<<dim3(EMBED / 128, MROWS / 128), 256, G_SMEM_BYTES>>>(
        att, wpT, bproj, out, MROWS, EMBED, EMBED);
}

// round 5
// speedup vs baseline: 1.2586x; 1.2586x over previous
#include <cuda_runtime.h>
#include <cuda_bf16.h>
#include <math.h>
#include <stdint.h>

// ---------------------------------------------------------------------------
// Problem constants
// ---------------------------------------------------------------------------
#define BATCH   4
#define SEQ     2048
#define EMBED   1024
#define HEADS   8
#define HDIM    128            // EMBED / HEADS
#define MROWS   (BATCH * SEQ)  // 8192
#define QKV_N   (3 * EMBED)    // 3072

// Scratch: __device__ globals (no allocation allowed anywhere)
__device__ float g_qkv[(size_t)BATCH * SEQ * QKV_N];   // [B,N,3D]
__device__ float g_att[(size_t)BATCH * SEQ * EMBED];   // [B,N,D]

// ---------------------------------------------------------------------------
// Packed f32x2 helpers (sm_100+ PTX; HW FFMA2 on sm_103a)
// ---------------------------------------------------------------------------
typedef unsigned long long u64;

__device__ __forceinline__ u64 pk2(float lo, float hi) {
    u64 r;
    asm("mov.b64 %0, {%1, %2};" : "=l"(r) : "f"(lo), "f"(hi));
    return r;
}
__device__ __forceinline__ float2 up2(u64 v) {
    float2 f;
    asm("mov.b64 {%0, %1}, %2;" : "=f"(f.x), "=f"(f.y) : "l"(v));
    return f;
}
__device__ __forceinline__ u64 f2fma(u64 a, u64 b, u64 c) {
    u64 d;
    asm("fma.rn.f32x2 %0, %1, %2, %3;" : "=l"(d) : "l"(a), "l"(b), "l"(c));
    return d;
}
__device__ __forceinline__ u64 f2mul(u64 a, u64 b) {
    u64 d;
    asm("mul.rn.f32x2 %0, %1, %2;" : "=l"(d) : "l"(a), "l"(b));
    return d;
}

// ---------------------------------------------------------------------------
// SGEMM with bias: C[M,N] = A[M,K] @ B[K,N] + bias[N]
// 128x128 block tile, K-tile 8, 256 threads, 8x8 per-thread microtile,
// inner product done with packed fma.rn.f32x2 (2 FMA / issue slot).
// ---------------------------------------------------------------------------
__global__ __launch_bounds__(256, 2)
void sgemm_bias_kernel(const float* __restrict__ A, const float* __restrict__ B,
                       const float* __restrict__ bias, float* __restrict__ C,
                       int M, int N, int K)
{
    __shared__ float As[8][128];   // As[kk][row]  (A tile transposed)
    __shared__ float Bs[8][128];   // Bs[kk][col]

    const int tid = threadIdx.x;
    const int bm = blockIdx.y * 128;
    const int bn = blockIdx.x * 128;
    const int tx = tid & 15;       // 16 col-groups
    const int ty = tid >> 4;       // 16 row-groups

    const int a_row = tid >> 1;          // 0..127
    const int a_col = (tid & 1) * 4;     // 0 or 4
    const int b_row = tid >> 5;          // 0..7
    const int b_col = (tid & 31) * 4;    // 0..124

    const float* Ap = A + (size_t)(bm + a_row) * K + a_col;
    const float* Bp = B + (size_t)b_row * N + bn + b_col;

    // acc2[i][jp] = packed pair (c[i][2jp], c[i][2jp+1])
    u64 acc2[8][4];
#pragma unroll
    for (int i = 0; i < 8; i++)
#pragma unroll
        for (int j = 0; j < 4; j++) acc2[i][j] = 0ull;

    for (int k0 = 0; k0 < K; k0 += 8) {
        float4 av = *reinterpret_cast<const float4*>(Ap + k0);
        float4 bv = *reinterpret_cast<const float4*>(Bp + (size_t)k0 * N);
        As[a_col + 0][a_row] = av.x;
        As[a_col + 1][a_row] = av.y;
        As[a_col + 2][a_row] = av.z;
        As[a_col + 3][a_row] = av.w;
        *reinterpret_cast<float4*>(&Bs[b_row][b_col]) = bv;
        __syncthreads();

#pragma unroll
        for (int kk = 0; kk < 8; kk++) {
            float4 a0 = *reinterpret_cast<const float4*>(&As[kk][ty * 4]);
            float4 a1 = *reinterpret_cast<const float4*>(&As[kk][64 + ty * 4]);
            ulonglong2 bp0 = *reinterpret_cast<const ulonglong2*>(&Bs[kk][tx * 4]);
            ulonglong2 bp1 = *reinterpret_cast<const ulonglong2*>(&Bs[kk][64 + tx * 4]);
            u64 bp[4] = {bp0.x, bp0.y, bp1.x, bp1.y};
            float ar[8] = {a0.x, a0.y, a0.z, a0.w, a1.x, a1.y, a1.z, a1.w};
#pragma unroll
            for (int i = 0; i < 8; i++) {
                u64 aa = pk2(ar[i], ar[i]);
#pragma unroll
                for (int j = 0; j < 4; j++)
                    acc2[i][j] = f2fma(aa, bp[j], acc2[i][j]);
            }
        }
        __syncthreads();
    }

    // epilogue
    float4 bi0 = *reinterpret_cast<const float4*>(&bias[bn + tx * 4]);
    float4 bi1 = *reinterpret_cast<const float4*>(&bias[bn + 64 + tx * 4]);
#pragma unroll
    for (int i = 0; i < 8; i++) {
        int rl = (i < 4) ? (ty * 4 + i) : (64 + ty * 4 + (i - 4));
        float* Crow = C + (size_t)(bm + rl) * N + bn;
        float2 c0 = up2(acc2[i][0]);
        float2 c1 = up2(acc2[i][1]);
        float2 c2 = up2(acc2[i][2]);
        float2 c3 = up2(acc2[i][3]);
        float4 o0, o1;
        o0.x = c0.x + bi0.x; o0.y = c0.y + bi0.y;
        o0.z = c1.x + bi0.z; o0.w = c1.y + bi0.w;
        o1.x = c2.x + bi1.x; o1.y = c2.y + bi1.y;
        o1.z = c3.x + bi1.z; o1.w = c3.y + bi1.w;
        *reinterpret_cast<float4*>(Crow + tx * 4) = o0;
        *reinterpret_cast<float4*>(Crow + 64 + tx * 4) = o1;
    }
}

// ---------------------------------------------------------------------------
// Flash attention (fp32, online softmax), f32x2 inner loops.
// Grid: (SEQ/64, HEADS, BATCH), 256 threads.
// Layout identical to the R1-passing version.
// ---------------------------------------------------------------------------
#define QS_OFF   0
#define KS_OFF   (128 * 68)                 // 8704
#define VS_OFF   (KS_OFF + 128 * 68)        // 17408
#define SS_OFF   (VS_OFF + 64 * 128)        // 25600
#define MS_OFF   (SS_OFF + 64 * 68)         // 29952
#define LS_OFF   (MS_OFF + 64)
#define CS_OFF   (LS_OFF + 64)
#define FA_SMEM_FLOATS (CS_OFF + 64)        // 30144
#define FA_SMEM_BYTES  (FA_SMEM_FLOATS * 4) // 120576 B

__global__ __launch_bounds__(256, 1)
void attention_kernel(const float* __restrict__ qkv, float* __restrict__ out)
{
    extern __shared__ float sm[];
    float* Qs  = sm + QS_OFF;
    float* Ks  = sm + KS_OFF;
    float* Vs  = sm + VS_OFF;
    float* Ss  = sm + SS_OFF;
    float* m_s = sm + MS_OFF;
    float* l_s = sm + LS_OFF;
    float* c_s = sm + CS_OFF;

    const int tid  = threadIdx.x;
    const int lane = tid & 31;
    const int warp = tid >> 5;
    const int tx   = tid & 15;
    const int ty   = tid >> 4;
    const int q0   = blockIdx.x * 64;
    const int h    = blockIdx.y;
    const int b    = blockIdx.z;

    const size_t base = (size_t)b * SEQ * QKV_N + (size_t)h * HDIM;
    const float* Qg = qkv + base;                // + row*QKV_N
    const float* Kg = qkv + base + EMBED;
    const float* Vg = qkv + base + 2 * EMBED;

    // ---- load Q tile transposed: Qs[d][qi] ----
    {
        const int d4 = (tid & 31) * 4;
#pragma unroll
        for (int pass = 0; pass < 8; pass++) {
            int qi = pass * 8 + warp;
            float4 v = *reinterpret_cast<const float4*>(
                Qg + (size_t)(q0 + qi) * QKV_N + d4);
            Qs[(d4 + 0) * 68 + qi] = v.x;
            Qs[(d4 + 1) * 68 + qi] = v.y;
            Qs[(d4 + 2) * 68 + qi] = v.z;
            Qs[(d4 + 3) * 68 + qi] = v.w;
        }
    }
    if (tid < 64) { m_s[tid] = -1e30f; l_s[tid] = 0.f; }

    // O accumulator packed: o2[i][jp] = (o[i][2jp], o[i][2jp+1])
    u64 o2[4][4];
#pragma unroll
    for (int i = 0; i < 4; i++)
#pragma unroll
        for (int j = 0; j < 4; j++) o2[i][j] = 0ull;

    const float sc = 0.08838834764831845f;   // 128^-0.5
    const u64 sc2 = pk2(sc, sc);

    for (int kt = 0; kt < SEQ / 64; kt++) {
        // ---- load K tile transposed, V tile row-major ----
        {
            const int d4 = (tid & 31) * 4;
#pragma unroll
            for (int pass = 0; pass < 8; pass++) {
                int ki = pass * 8 + warp;
                size_t grow = (size_t)(kt * 64 + ki) * QKV_N + d4;
                float4 kv = *reinterpret_cast<const float4*>(Kg + grow);
                Ks[(d4 + 0) * 68 + ki] = kv.x;
                Ks[(d4 + 1) * 68 + ki] = kv.y;
                Ks[(d4 + 2) * 68 + ki] = kv.z;
                Ks[(d4 + 3) * 68 + ki] = kv.w;
                float4 vv = *reinterpret_cast<const float4*>(Vg + grow);
                *reinterpret_cast<float4*>(&Vs[ki * 128 + d4]) = vv;
            }
        }
        __syncthreads();

        // ---- S = (Q^T K) tile: thread 4x4 at rows ty*4.., cols tx*4..
        //      packed: s2[i][jp] = (s[i][2jp], s[i][2jp+1]) ----
        u64 s2[4][2];
#pragma unroll
        for (int i = 0; i < 4; i++) { s2[i][0] = 0ull; s2[i][1] = 0ull; }

#pragma unroll 4
        for (int kk = 0; kk < 128; kk++) {
            float4 qv = *reinterpret_cast<const float4*>(&Qs[kk * 68 + ty * 4]);
            ulonglong2 kp = *reinterpret_cast<const ulonglong2*>(&Ks[kk * 68 + tx * 4]);
            float qr[4] = {qv.x, qv.y, qv.z, qv.w};
#pragma unroll
            for (int i = 0; i < 4; i++) {
                u64 aa = pk2(qr[i], qr[i]);
                s2[i][0] = f2fma(aa, kp.x, s2[i][0]);
                s2[i][1] = f2fma(aa, kp.y, s2[i][1]);
            }
        }
#pragma unroll
        for (int i = 0; i < 4; i++) {
            ulonglong2 sv;
            sv.x = f2mul(s2[i][0], sc2);
            sv.y = f2mul(s2[i][1], sc2);
            *reinterpret_cast<ulonglong2*>(&Ss[(ty * 4 + i) * 68 + tx * 4]) = sv;
        }
        __syncthreads();

        // ---- online softmax: warp w owns rows w*8..w*8+7 ----
#pragma unroll
        for (int rr = 0; rr < 8; rr++) {
            int r = warp * 8 + rr;
            float x0 = Ss[r * 68 + lane];
            float x1 = Ss[r * 68 + 32 + lane];
            float mx = fmaxf(x0, x1);
#pragma unroll
            for (int off = 16; off > 0; off >>= 1)
                mx = fmaxf(mx, __shfl_xor_sync(0xffffffffu, mx, off));
            float mo = m_s[r];
            float M  = fmaxf(mo, mx);
            float p0 = __expf(x0 - M);
            float p1 = __expf(x1 - M);
            Ss[r * 68 + lane]      = p0;
            Ss[r * 68 + 32 + lane] = p1;
            float sum = p0 + p1;
#pragma unroll
            for (int off = 16; off > 0; off >>= 1)
                sum += __shfl_xor_sync(0xffffffffu, sum, off);
            if (lane == 0) {
                float corr = __expf(mo - M);
                l_s[r] = l_s[r] * corr + sum;
                m_s[r] = M;
                c_s[r] = corr;
            }
        }
        __syncthreads();

        // ---- rescale O, then O += P @ V (packed) ----
#pragma unroll
        for (int i = 0; i < 4; i++) {
            float c = c_s[ty * 4 + i];
            u64 cc = pk2(c, c);
#pragma unroll
            for (int j = 0; j < 4; j++) o2[i][j] = f2mul(o2[i][j], cc);
        }

#pragma unroll 4
        for (int ki = 0; ki < 64; ki++) {
            float p0 = Ss[(ty * 4 + 0) * 68 + ki];
            float p1 = Ss[(ty * 4 + 1) * 68 + ki];
            float p2 = Ss[(ty * 4 + 2) * 68 + ki];
            float p3 = Ss[(ty * 4 + 3) * 68 + ki];
            ulonglong2 va = *reinterpret_cast<const ulonglong2*>(&Vs[ki * 128 + tx * 4]);
            ulonglong2 vb = *reinterpret_cast<const ulonglong2*>(&Vs[ki * 128 + 64 + tx * 4]);
            u64 vp[4] = {va.x, va.y, vb.x, vb.y};
            float pr[4] = {p0, p1, p2, p3};
#pragma unroll
            for (int i = 0; i < 4; i++) {
                u64 pp = pk2(pr[i], pr[i]);
#pragma unroll
                for (int j = 0; j < 4; j++)
                    o2[i][j] = f2fma(pp, vp[j], o2[i][j]);
            }
        }
        __syncthreads();
    }

    // ---- epilogue: divide by l, write merged-head layout ----
#pragma unroll
    for (int i = 0; i < 4; i++) {
        int r = ty * 4 + i;
        float inv = 1.f / l_s[r];
        float* orow = out + ((size_t)b * SEQ + (q0 + r)) * EMBED + h * HDIM;
        float2 c0 = up2(o2[i][0]);
        float2 c1 = up2(o2[i][1]);
        float2 c2 = up2(o2[i][2]);
        float2 c3 = up2(o2[i][3]);
        float4 o0, o1;
        o0.x = c0.x * inv; o0.y = c0.y * inv;
        o0.z = c1.x * inv; o0.w = c1.y * inv;
        o1.x = c2.x * inv; o1.y = c2.y * inv;
        o1.z = c3.x * inv; o1.w = c3.y * inv;
        *reinterpret_cast<float4*>(orow + tx * 4)      = o0;
        *reinterpret_cast<float4*>(orow + 64 + tx * 4) = o1;
    }
}

// ---------------------------------------------------------------------------
// Launch: GEMM1 (QKV) -> attention -> GEMM2 (proj). Same stream, capturable.
// ---------------------------------------------------------------------------
extern "C" void kernel_launch(void* const* d_in, const int* in_sizes, int n_in,
                              void* d_out, int out_size)
{
    const float* x     = (const float*)d_in[0];   // [4,2048,1024]
    const float* Wqkv  = (const float*)d_in[1];   // [1024,3072]
    const float* bqkv  = (const float*)d_in[2];   // [3072]
    const float* Wproj = (const float*)d_in[3];   // [1024,1024]
    const float* bproj = (const float*)d_in[4];   // [1024]
    float* out = (float*)d_out;

    void* p_qkv = nullptr;
    void* p_att = nullptr;
    cudaGetSymbolAddress(&p_qkv, g_qkv);
    cudaGetSymbolAddress(&p_att, g_att);
    float* qkv = (float*)p_qkv;
    float* att = (float*)p_att;

    // GEMM1: [8192,1024] @ [1024,3072] + b -> qkv
    sgemm_bias_kernel<<<dim3(QKV_N / 128, MROWS / 128), 256>>>(
        x, Wqkv, bqkv, qkv, MROWS, QKV_N, EMBED);

    // Attention
    cudaFuncSetAttribute(attention_kernel,
                         cudaFuncAttributeMaxDynamicSharedMemorySize,
                         FA_SMEM_BYTES);
    attention_kernel<<<dim3(SEQ / 64, HEADS, BATCH), 256, FA_SMEM_BYTES>>>(
        qkv, att);

    // GEMM2: [8192,1024] @ [1024,1024] + b -> out
    sgemm_bias_kernel<<<dim3(EMBED / 128, MROWS / 128), 256>>>(
        att, Wproj, bproj, out, MROWS, EMBED, EMBED);
}

// round 6
// speedup vs baseline: 1.4399x; 1.1441x over previous
#include <cuda_runtime.h>
#include <cuda_bf16.h>
#include <math.h>
#include <stdint.h>

// ---------------------------------------------------------------------------
// Problem constants
// ---------------------------------------------------------------------------
#define BATCH   4
#define SEQ     2048
#define EMBED   1024
#define HEADS   8
#define HDIM    128            // EMBED / HEADS
#define MROWS   (BATCH * SEQ)  // 8192
#define QKV_N   (3 * EMBED)    // 3072

// Scratch: __device__ globals (no allocation allowed anywhere)
__device__ float g_qkv[(size_t)BATCH * SEQ * QKV_N];   // [B,N,3D]
__device__ float g_att[(size_t)BATCH * SEQ * EMBED];   // [B,N,D]

// ---------------------------------------------------------------------------
// Packed f32x2 helpers (sm_100+ PTX; FFMA2 on sm_103a — 2 FMA per issue slot)
// ---------------------------------------------------------------------------
typedef unsigned long long u64;

__device__ __forceinline__ u64 pk2(float lo, float hi) {
    u64 r;
    asm("mov.b64 %0, {%1, %2};" : "=l"(r) : "f"(lo), "f"(hi));
    return r;
}
__device__ __forceinline__ float2 up2(u64 v) {
    float2 f;
    asm("mov.b64 {%0, %1}, %2;" : "=f"(f.x), "=f"(f.y) : "l"(v));
    return f;
}
__device__ __forceinline__ u64 f2fma(u64 a, u64 b, u64 c) {
    u64 d;
    asm("fma.rn.f32x2 %0, %1, %2, %3;" : "=l"(d) : "l"(a), "l"(b), "l"(c));
    return d;
}
__device__ __forceinline__ u64 f2mul(u64 a, u64 b) {
    u64 d;
    asm("mul.rn.f32x2 %0, %1, %2;" : "=l"(d) : "l"(a), "l"(b));
    return d;
}

// ---------------------------------------------------------------------------
// SGEMM with bias: C[M,N] = A[M,K] @ B[K,N] + bias[N]
// 128x128 block tile, K-tile 16, double-buffered smem, register prefetch.
// One __syncthreads per K-tile; LDGs for tile t+1 overlap compute of tile t.
// ---------------------------------------------------------------------------
#define TK 16

__global__ __launch_bounds__(256, 2)
void sgemm_bias_kernel(const float* __restrict__ A, const float* __restrict__ B,
                       const float* __restrict__ bias, float* __restrict__ C,
                       int M, int N, int K)
{
    __shared__ float As[2][TK][128];   // As[buf][kk][row]  (transposed)
    __shared__ float Bs[2][TK][128];   // Bs[buf][kk][col]

    const int tid = threadIdx.x;
    const int bm = blockIdx.y * 128;
    const int bn = blockIdx.x * 128;
    const int tx = tid & 15;       // 16 col-groups
    const int ty = tid >> 4;       // 16 row-groups

    // load mapping: A -> thread owns (row = tid>>1, k = (tid&1)*8 .. +7)
    //               B -> thread owns (k = tid>>4,  col = (tid&15)*8 .. +7)
    const int a_row = tid >> 1;
    const int a_k   = (tid & 1) * 8;
    const int b_k   = tid >> 4;
    const int b_c   = (tid & 15) * 8;

    const float* Ap = A + (size_t)(bm + a_row) * K + a_k;
    const float* Bp = B + (size_t)b_k * N + bn + b_c;

    // acc2[i][jp] = packed pair (c[i][2jp], c[i][2jp+1])
    u64 acc2[8][4];
#pragma unroll
    for (int i = 0; i < 8; i++)
#pragma unroll
        for (int j = 0; j < 4; j++) acc2[i][j] = 0ull;

    const int NT = K / TK;

    float4 a0 = *reinterpret_cast<const float4*>(Ap);
    float4 a1 = *reinterpret_cast<const float4*>(Ap + 4);
    float4 b0 = *reinterpret_cast<const float4*>(Bp);
    float4 b1 = *reinterpret_cast<const float4*>(Bp + 4);

    for (int t = 0; t < NT; t++) {
        const int buf = t & 1;
        // stores of tile t (regs -> smem)
        As[buf][a_k + 0][a_row] = a0.x;
        As[buf][a_k + 1][a_row] = a0.y;
        As[buf][a_k + 2][a_row] = a0.z;
        As[buf][a_k + 3][a_row] = a0.w;
        As[buf][a_k + 4][a_row] = a1.x;
        As[buf][a_k + 5][a_row] = a1.y;
        As[buf][a_k + 6][a_row] = a1.z;
        As[buf][a_k + 7][a_row] = a1.w;
        *reinterpret_cast<float4*>(&Bs[buf][b_k][b_c])     = b0;
        *reinterpret_cast<float4*>(&Bs[buf][b_k][b_c + 4]) = b1;
        __syncthreads();

        // prefetch tile t+1 (LDGs overlap the compute below)
        if (t + 1 < NT) {
            const float* Apn = Ap + (t + 1) * TK;
            const float* Bpn = Bp + (size_t)(t + 1) * TK * N;
            a0 = *reinterpret_cast<const float4*>(Apn);
            a1 = *reinterpret_cast<const float4*>(Apn + 4);
            b0 = *reinterpret_cast<const float4*>(Bpn);
            b1 = *reinterpret_cast<const float4*>(Bpn + 4);
        }

#pragma unroll
        for (int kk = 0; kk < TK; kk++) {
            float4 av0 = *reinterpret_cast<const float4*>(&As[buf][kk][ty * 4]);
            float4 av1 = *reinterpret_cast<const float4*>(&As[buf][kk][64 + ty * 4]);
            ulonglong2 bp0 = *reinterpret_cast<const ulonglong2*>(&Bs[buf][kk][tx * 4]);
            ulonglong2 bp1 = *reinterpret_cast<const ulonglong2*>(&Bs[buf][kk][64 + tx * 4]);
            u64 bp[4] = {bp0.x, bp0.y, bp1.x, bp1.y};
            float ar[8] = {av0.x, av0.y, av0.z, av0.w, av1.x, av1.y, av1.z, av1.w};
#pragma unroll
            for (int i = 0; i < 8; i++) {
                u64 aa = pk2(ar[i], ar[i]);
#pragma unroll
                for (int j = 0; j < 4; j++)
                    acc2[i][j] = f2fma(aa, bp[j], acc2[i][j]);
            }
        }
    }

    // epilogue
    float4 bi0 = *reinterpret_cast<const float4*>(&bias[bn + tx * 4]);
    float4 bi1 = *reinterpret_cast<const float4*>(&bias[bn + 64 + tx * 4]);
#pragma unroll
    for (int i = 0; i < 8; i++) {
        int rl = (i < 4) ? (ty * 4 + i) : (64 + ty * 4 + (i - 4));
        float* Crow = C + (size_t)(bm + rl) * N + bn;
        float2 c0 = up2(acc2[i][0]);
        float2 c1 = up2(acc2[i][1]);
        float2 c2 = up2(acc2[i][2]);
        float2 c3 = up2(acc2[i][3]);
        float4 o0, o1;
        o0.x = c0.x + bi0.x; o0.y = c0.y + bi0.y;
        o0.z = c1.x + bi0.z; o0.w = c1.y + bi0.w;
        o1.x = c2.x + bi1.x; o1.y = c2.y + bi1.y;
        o1.z = c3.x + bi1.z; o1.w = c3.y + bi1.w;
        *reinterpret_cast<float4*>(Crow + tx * 4) = o0;
        *reinterpret_cast<float4*>(Crow + 64 + tx * 4) = o1;
    }
}

// ---------------------------------------------------------------------------
// Flash attention (fp32, online softmax), f32x2 inner loops,
// software-pipelined K/V tile loads:
//   S -> sync -> issue LDG(kt+1) -> softmax -> sync -> STS K -> PV -> sync -> STS V
// ---------------------------------------------------------------------------
#define QS_OFF   0
#define KS_OFF   (128 * 68)                 // 8704
#define VS_OFF   (KS_OFF + 128 * 68)        // 17408
#define SS_OFF   (VS_OFF + 64 * 128)        // 25600
#define MS_OFF   (SS_OFF + 64 * 68)         // 29952
#define LS_OFF   (MS_OFF + 64)
#define CS_OFF   (LS_OFF + 64)
#define FA_SMEM_FLOATS (CS_OFF + 64)        // 30144
#define FA_SMEM_BYTES  (FA_SMEM_FLOATS * 4) // 120576 B

__global__ __launch_bounds__(256, 1)
void attention_kernel(const float* __restrict__ qkv, float* __restrict__ out)
{
    extern __shared__ float sm[];
    float* Qs  = sm + QS_OFF;
    float* Ks  = sm + KS_OFF;
    float* Vs  = sm + VS_OFF;
    float* Ss  = sm + SS_OFF;
    float* m_s = sm + MS_OFF;
    float* l_s = sm + LS_OFF;
    float* c_s = sm + CS_OFF;

    const int tid  = threadIdx.x;
    const int lane = tid & 31;
    const int warp = tid >> 5;
    const int tx   = tid & 15;
    const int ty   = tid >> 4;
    const int q0   = blockIdx.x * 64;
    const int h    = blockIdx.y;
    const int b    = blockIdx.z;

    const size_t base = (size_t)b * SEQ * QKV_N + (size_t)h * HDIM;
    const float* Qg = qkv + base;                // + row*QKV_N
    const float* Kg = qkv + base + EMBED;
    const float* Vg = qkv + base + 2 * EMBED;

    const int d4 = (tid & 31) * 4;

    // ---- prologue: load Q tile (transposed) and K/V tile 0 ----
    {
#pragma unroll
        for (int pass = 0; pass < 8; pass++) {
            int qi = pass * 8 + warp;
            float4 v = *reinterpret_cast<const float4*>(
                Qg + (size_t)(q0 + qi) * QKV_N + d4);
            Qs[(d4 + 0) * 68 + qi] = v.x;
            Qs[(d4 + 1) * 68 + qi] = v.y;
            Qs[(d4 + 2) * 68 + qi] = v.z;
            Qs[(d4 + 3) * 68 + qi] = v.w;

            size_t grow = (size_t)pass * 8 * QKV_N + (size_t)warp * QKV_N + d4;
            float4 kv = *reinterpret_cast<const float4*>(Kg + grow);
            int ki = pass * 8 + warp;
            Ks[(d4 + 0) * 68 + ki] = kv.x;
            Ks[(d4 + 1) * 68 + ki] = kv.y;
            Ks[(d4 + 2) * 68 + ki] = kv.z;
            Ks[(d4 + 3) * 68 + ki] = kv.w;
            float4 vv = *reinterpret_cast<const float4*>(Vg + grow);
            *reinterpret_cast<float4*>(&Vs[ki * 128 + d4]) = vv;
        }
    }
    if (tid < 64) { m_s[tid] = -1e30f; l_s[tid] = 0.f; }
    __syncthreads();

    // O accumulator packed
    u64 o2[4][4];
#pragma unroll
    for (int i = 0; i < 4; i++)
#pragma unroll
        for (int j = 0; j < 4; j++) o2[i][j] = 0ull;

    const float sc = 0.08838834764831845f;   // 128^-0.5
    const u64 sc2 = pk2(sc, sc);

    const int NT = SEQ / 64;   // 32
    float4 kf[8], vf[8];

    for (int kt = 0; kt < NT; kt++) {
        // ---- S = (Q^T K) tile (packed f32x2) ----
        u64 s2[4][2];
#pragma unroll
        for (int i = 0; i < 4; i++) { s2[i][0] = 0ull; s2[i][1] = 0ull; }

#pragma unroll 4
        for (int kk = 0; kk < 128; kk++) {
            float4 qv = *reinterpret_cast<const float4*>(&Qs[kk * 68 + ty * 4]);
            ulonglong2 kp = *reinterpret_cast<const ulonglong2*>(&Ks[kk * 68 + tx * 4]);
            float qr[4] = {qv.x, qv.y, qv.z, qv.w};
#pragma unroll
            for (int i = 0; i < 4; i++) {
                u64 aa = pk2(qr[i], qr[i]);
                s2[i][0] = f2fma(aa, kp.x, s2[i][0]);
                s2[i][1] = f2fma(aa, kp.y, s2[i][1]);
            }
        }
#pragma unroll
        for (int i = 0; i < 4; i++) {
            ulonglong2 sv;
            sv.x = f2mul(s2[i][0], sc2);
            sv.y = f2mul(s2[i][1], sc2);
            *reinterpret_cast<ulonglong2*>(&Ss[(ty * 4 + i) * 68 + tx * 4]) = sv;
        }
        __syncthreads();   // S visible; Ks now dead for this iteration

        // ---- prefetch tile kt+1 into registers (latency hidden below) ----
        if (kt + 1 < NT) {
#pragma unroll
            for (int pass = 0; pass < 8; pass++) {
                int ki = pass * 8 + warp;
                size_t grow = (size_t)((kt + 1) * 64 + ki) * QKV_N + d4;
                kf[pass] = *reinterpret_cast<const float4*>(Kg + grow);
                vf[pass] = *reinterpret_cast<const float4*>(Vg + grow);
            }
        }

        // ---- online softmax: warp w owns rows w*8..w*8+7 ----
#pragma unroll
        for (int rr = 0; rr < 8; rr++) {
            int r = warp * 8 + rr;
            float x0 = Ss[r * 68 + lane];
            float x1 = Ss[r * 68 + 32 + lane];
            float mx = fmaxf(x0, x1);
#pragma unroll
            for (int off = 16; off > 0; off >>= 1)
                mx = fmaxf(mx, __shfl_xor_sync(0xffffffffu, mx, off));
            float mo = m_s[r];
            float M  = fmaxf(mo, mx);
            float p0 = __expf(x0 - M);
            float p1 = __expf(x1 - M);
            Ss[r * 68 + lane]      = p0;
            Ss[r * 68 + 32 + lane] = p1;
            float sum = p0 + p1;
#pragma unroll
            for (int off = 16; off > 0; off >>= 1)
                sum += __shfl_xor_sync(0xffffffffu, sum, off);
            if (lane == 0) {
                float corr = __expf(mo - M);
                l_s[r] = l_s[r] * corr + sum;
                m_s[r] = M;
                c_s[r] = corr;
            }
        }
        __syncthreads();   // P, c_s visible

        // ---- drain K prefetch into Ks (dead until next S, after next sync) ----
        if (kt + 1 < NT) {
#pragma unroll
            for (int pass = 0; pass < 8; pass++) {
                int ki = pass * 8 + warp;
                Ks[(d4 + 0) * 68 + ki] = kf[pass].x;
                Ks[(d4 + 1) * 68 + ki] = kf[pass].y;
                Ks[(d4 + 2) * 68 + ki] = kf[pass].z;
                Ks[(d4 + 3) * 68 + ki] = kf[pass].w;
            }
        }

        // ---- rescale O, then O += P @ V (packed) ----
#pragma unroll
        for (int i = 0; i < 4; i++) {
            float c = c_s[ty * 4 + i];
            u64 cc = pk2(c, c);
#pragma unroll
            for (int j = 0; j < 4; j++) o2[i][j] = f2mul(o2[i][j], cc);
        }

#pragma unroll 4
        for (int ki = 0; ki < 64; ki++) {
            float p0 = Ss[(ty * 4 + 0) * 68 + ki];
            float p1 = Ss[(ty * 4 + 1) * 68 + ki];
            float p2 = Ss[(ty * 4 + 2) * 68 + ki];
            float p3 = Ss[(ty * 4 + 3) * 68 + ki];
            ulonglong2 va = *reinterpret_cast<const ulonglong2*>(&Vs[ki * 128 + tx * 4]);
            ulonglong2 vb = *reinterpret_cast<const ulonglong2*>(&Vs[ki * 128 + 64 + tx * 4]);
            u64 vp[4] = {va.x, va.y, vb.x, vb.y};
            float pr[4] = {p0, p1, p2, p3};
#pragma unroll
            for (int i = 0; i < 4; i++) {
                u64 pp = pk2(pr[i], pr[i]);
#pragma unroll
                for (int j = 0; j < 4; j++)
                    o2[i][j] = f2fma(pp, vp[j], o2[i][j]);
            }
        }
        __syncthreads();   // PV done (Vs dead), K stores done before next S

        // ---- drain V prefetch into Vs (visible by next iteration's syncs) ----
        if (kt + 1 < NT) {
#pragma unroll
            for (int pass = 0; pass < 8; pass++) {
                int ki = pass * 8 + warp;
                *reinterpret_cast<float4*>(&Vs[ki * 128 + d4]) = vf[pass];
            }
        }
    }

    // ---- epilogue: divide by l, write merged-head layout ----
#pragma unroll
    for (int i = 0; i < 4; i++) {
        int r = ty * 4 + i;
        float inv = 1.f / l_s[r];
        float* orow = out + ((size_t)b * SEQ + (q0 + r)) * EMBED + h * HDIM;
        float2 c0 = up2(o2[i][0]);
        float2 c1 = up2(o2[i][1]);
        float2 c2 = up2(o2[i][2]);
        float2 c3 = up2(o2[i][3]);
        float4 o0, o1;
        o0.x = c0.x * inv; o0.y = c0.y * inv;
        o0.z = c1.x * inv; o0.w = c1.y * inv;
        o1.x = c2.x * inv; o1.y = c2.y * inv;
        o1.z = c3.x * inv; o1.w = c3.y * inv;
        *reinterpret_cast<float4*>(orow + tx * 4)      = o0;
        *reinterpret_cast<float4*>(orow + 64 + tx * 4) = o1;
    }
}

// ---------------------------------------------------------------------------
// Launch: GEMM1 (QKV) -> attention -> GEMM2 (proj). Same stream, capturable.
// ---------------------------------------------------------------------------
extern "C" void kernel_launch(void* const* d_in, const int* in_sizes, int n_in,
                              void* d_out, int out_size)
{
    const float* x     = (const float*)d_in[0];   // [4,2048,1024]
    const float* Wqkv  = (const float*)d_in[1];   // [1024,3072]
    const float* bqkv  = (const float*)d_in[2];   // [3072]
    const float* Wproj = (const float*)d_in[3];   // [1024,1024]
    const float* bproj = (const float*)d_in[4];   // [1024]
    float* out = (float*)d_out;

    void* p_qkv = nullptr;
    void* p_att = nullptr;
    cudaGetSymbolAddress(&p_qkv, g_qkv);
    cudaGetSymbolAddress(&p_att, g_att);
    float* qkv = (float*)p_qkv;
    float* att = (float*)p_att;

    // GEMM1: [8192,1024] @ [1024,3072] + b -> qkv
    sgemm_bias_kernel<<<dim3(QKV_N / 128, MROWS / 128), 256>>>(
        x, Wqkv, bqkv, qkv, MROWS, QKV_N, EMBED);

    // Attention
    cudaFuncSetAttribute(attention_kernel,
                         cudaFuncAttributeMaxDynamicSharedMemorySize,
                         FA_SMEM_BYTES);
    attention_kernel<<<dim3(SEQ / 64, HEADS, BATCH), 256, FA_SMEM_BYTES>>>(
        qkv, att);

    // GEMM2: [8192,1024] @ [1024,1024] + b -> out
    sgemm_bias_kernel<<<dim3(EMBED / 128, MROWS / 128), 256>>>(
        att, Wproj, bproj, out, MROWS, EMBED, EMBED);
}